// round 4
// baseline (speedup 1.0000x reference)
#include <cuda_runtime.h>
#include <cmath>
#include <cstdint>

// ---------------- problem constants ----------------
#define HW   4096
#define SB   (64*HW)
#define NB   4
#define T_IN 10
#define STEPS 18
#define STATE_ELEMS (NB*64*HW)
#define YBUF_ELEMS  (NB*32*HW)

// ---------------- device scratch ----------------
__device__ float g_sx0[3*2*STATE_ELEMS];
__device__ float g_sz [3*2*STATE_ELEMS];
__device__ float g_sx1[3*STATE_ELEMS];
__device__ float g_sx2[3*STATE_ELEMS];
__device__ float g_y  [2*3*YBUF_ELEMS];
__device__ float g_pred[STEPS*NB*HW];

// transposed weights: [set][cin][tap][gate'] gate' = chunk*16 + j*4 + g  (8 chunks)
__device__ float g_wx0t[3*65*9*128];
__device__ float g_wz0t[3*65*25*128];
__device__ float g_wx1t[6*96*9*128];
__device__ float g_wz1t[6*96*25*128];

__device__ __forceinline__ float sigf(float x) { return 1.0f / (1.0f + expf(-x)); }

__device__ __forceinline__ unsigned sptr(const void* p) {
    return (unsigned)__cvta_generic_to_shared(p);
}
__device__ __forceinline__ void cpa4(unsigned d, const void* s, bool ok) {
    asm volatile("cp.async.ca.shared.global [%0], [%1], 4, %2;" :: "r"(d), "l"(s), "r"(ok ? 4 : 0));
}
__device__ __forceinline__ void cpa16(unsigned d, const void* s) {
    asm volatile("cp.async.cg.shared.global [%0], [%1], 16;" :: "r"(d), "l"(s));
}
#define CP_COMMIT() asm volatile("cp.async.commit_group;")
template<int N> __device__ __forceinline__ void cp_wait() {
    asm volatile("cp.async.wait_group %0;" :: "n"(N));
}
#define FFMA2(acc, a, b) asm("fma.rn.f32x2 %0, %1, %2, %0;" : "+l"(acc) : "l"(a), "l"(b))

// ---------------- fused weight pre-transpose (ONE launch) ----------------
// gp = chunk*16 + j*4 + g  (chunk 0..7, j 0..3, g 0..3); hid = chunk*4+j; gc = g*32 + hid
__device__ __forceinline__ void transpose_one(const float* __restrict__ src,
                                              float* __restrict__ dst,
                                              int cin, int kk, long i)
{
    int gp = (int)(i & 127);
    long r = i >> 7;
    int tap = (int)(r % kk); r /= kk;
    int ci  = (int)(r % cin);
    int set = (int)(r / cin);
    int chunk = gp >> 4, rem = gp & 15, j = rem >> 2, g = rem & 3;
    int gc = g * 32 + chunk * 4 + j;
    dst[i] = src[(((long)set * 128 + gc) * cin + ci) * kk + tap];
}

#define NA  ((long)3*65*9*128)
#define NBW ((long)3*65*25*128)
#define NC  ((long)6*96*9*128)
#define ND  ((long)6*96*25*128)

__global__ void transpose_all(const float* __restrict__ wx0, const float* __restrict__ wz0,
                              const float* __restrict__ wx1, const float* __restrict__ wz1,
                              float* __restrict__ dx0, float* __restrict__ dz0,
                              float* __restrict__ dx1, float* __restrict__ dz1)
{
    long i = (long)blockIdx.x * 256 + threadIdx.x;
    if (i < NA)  { transpose_one(wx0, dx0, 65, 9,  i); return; }
    i -= NA;
    if (i < NBW) { transpose_one(wz0, dz0, 65, 25, i); return; }
    i -= NBW;
    if (i < NC)  { transpose_one(wx1, dx1, 96, 9,  i); return; }
    i -= NC;
    if (i < ND)  { transpose_one(wz1, dz1, 96, 25, i); }
}

// ---------------- fused conv + LSTM gating (one branch, 2 px/thread, 16 gates) ----------------
#define TSTRIDE 48
template<int K, int CINX>
__device__ __forceinline__ void conv_branch(
    const float* __restrict__ x, int xbs,
    const float* __restrict__ hx, const float* __restrict__ hz,
    const float* __restrict__ cstate,
    const float* __restrict__ wt, const float* __restrict__ bias,
    float* __restrict__ dst,
    float* tileb, float* wb, int b, int chunk, int xt, int yt)
{
    constexpr int KK = K * K, PAD = K / 2;
    constexpr int TSX = 32 + K - 1, TSY = 16 + K - 1;
    constexpr int CIN = CINX + 64;
    constexpr int WSZ = KK * 16;
    const int tx = threadIdx.x & 15, ty = threadIdx.x >> 4, tid = threadIdx.x;
    const int gx0 = xt * 32 - PAD, gy0 = yt * 16 - PAD;

    auto chanptr = [&](int c) -> const float* {
        if (c < CINX)            return x  + (long)b * xbs + c * HW;
        else if (c < CINX + 32)  return hx + (long)b * SB + (c - CINX) * HW;
        else                     return hz + (long)b * SB + (c - CINX - 32) * HW;
    };
    auto prefetch = [&](int c, int buf) {
        const float* p = chanptr(c);
        float* tb = tileb + buf * (20 * TSTRIDE);
#pragma unroll
        for (int i = tid; i < TSY * TSX; i += 256) {
            int iy = i / TSX, ix = i - iy * TSX;
            int yy = gy0 + iy, xx = gx0 + ix;
            bool ok = (yy >= 0 && yy < 64 && xx >= 0 && xx < 64);
            cpa4(sptr(tb + iy * TSTRIDE + ix), ok ? p + yy * 64 + xx : p, ok);
        }
        if (tid < KK * 4) {
            int tap = tid >> 2, off = tid & 3;
            const float* src = wt + (((long)c * KK + tap) << 7) + chunk * 16 + off * 4;
            cpa16(sptr(wb + buf * WSZ + tap * 16 + off * 4), src);
        }
        CP_COMMIT();
    };

    unsigned long long a0[8], a1[8];
#pragma unroll
    for (int i = 0; i < 8; i++) { a0[i] = 0ull; a1[i] = 0ull; }

    prefetch(0, 0);
    for (int c = 0; c < CIN; ++c) {
        if (c + 1 < CIN) { prefetch(c + 1, (c + 1) % 3); cp_wait<1>(); }
        else             { cp_wait<0>(); }
        __syncthreads();
        const float* tb = tileb + (c % 3) * (20 * TSTRIDE);
        const float* wp = wb + (c % 3) * WSZ;
#pragma unroll
        for (int ky = 0; ky < K; ++ky)
#pragma unroll
        for (int kx = 0; kx < K; ++kx) {
            float v0 = tb[(ty + ky) * TSTRIDE + tx + kx];
            float v1 = tb[(ty + ky) * TSTRIDE + tx + 16 + kx];
            unsigned long long vv0, vv1;
            asm("mov.b64 %0, {%1, %1};" : "=l"(vv0) : "f"(v0));
            asm("mov.b64 %0, {%1, %1};" : "=l"(vv1) : "f"(v1));
            const ulonglong2* wq = (const ulonglong2*)(wp + (ky * K + kx) * 16);
#pragma unroll
            for (int p = 0; p < 4; p++) {
                ulonglong2 w2 = wq[p];
                FFMA2(a0[2 * p],     vv0, w2.x);
                FFMA2(a0[2 * p + 1], vv0, w2.y);
                FFMA2(a1[2 * p],     vv1, w2.x);
                FFMA2(a1[2 * p + 1], vv1, w2.y);
            }
        }
    }

    const int pix0 = (yt * 16 + ty) * 64 + xt * 32 + tx;
#pragma unroll
    for (int j = 0; j < 4; j++) {
        int hid = chunk * 4 + j;
        float bi = bias[hid], bf = bias[32 + hid] + 0.01f, bg = bias[64 + hid], bo = bias[96 + hid];
#pragma unroll
        for (int px = 0; px < 2; px++) {
            float ai, af, ag, ao;
            unsigned long long lo = px ? a1[2 * j] : a0[2 * j];
            unsigned long long hi = px ? a1[2 * j + 1] : a0[2 * j + 1];
            asm("mov.b64 {%0, %1}, %2;" : "=f"(ai), "=f"(af) : "l"(lo));
            asm("mov.b64 {%0, %1}, %2;" : "=f"(ag), "=f"(ao) : "l"(hi));
            int pix = pix0 + px * 16;
            float gi = sigf(ai + bi);
            float gf = sigf(af + bf);
            float gg = tanhf(ag + bg);
            float go = sigf(ao + bo);
            float cold = cstate[(long)b * SB + (32 + hid) * HW + pix];
            float cnew = gf * cold + gi * gg;
            dst[(long)b * SB + hid * HW + pix]        = go * tanhf(cnew);
            dst[(long)b * SB + (32 + hid) * HW + pix] = cnew;
        }
    }
}

// ---------------- fused cell kernel ----------------
// 512 blocks, 4/SM. branch = bit2 of bid -> each SM's resident set is 2xK3 + 2xK5.
template<int CINX>
__global__ __launch_bounds__(256, 4) void cell_kernel(
    const float* __restrict__ x, int xbs,
    const float* __restrict__ srcx, const float* __restrict__ srcz,
    const float* __restrict__ wxt, const float* __restrict__ bx,
    const float* __restrict__ wzt, const float* __restrict__ bz,
    float* __restrict__ dstx, float* __restrict__ dstz)
{
    __shared__ float tileb[3 * 20 * TSTRIDE];
    __shared__ __align__(16) float wb[3 * 400];
    const int bid = blockIdx.x;
    const int branch = (bid >> 2) & 1;
    const int r = (bid & 3) | ((bid >> 3) << 2);   // 8 bits -> 0..255
    const int xt = r & 1, yt = (r >> 1) & 3, b = (r >> 3) & 3, chunk = (r >> 5) & 7;
    if (branch == 0)
        conv_branch<3, CINX>(x, xbs, srcx, srcz, srcx, wxt, bx, dstx, tileb, wb, b, chunk, xt, yt);
    else
        conv_branch<5, CINX>(x, xbs, srcx, srcz, srcz, wzt, bz, dstz, tileb, wb, b, chunk, xt, yt);
}

// ---------------- 1x1 output conv ----------------
__global__ __launch_bounds__(128) void conv_y_kernel(
    const float* __restrict__ hx2, const float* __restrict__ hz2,
    const float* __restrict__ wy, const float* __restrict__ by,
    float* __restrict__ y)
{
    __shared__ float wsm[32 * 64];
    const int tid = threadIdx.x;
    for (int i = tid; i < 2048; i += 128) wsm[i] = wy[i];
    __syncthreads();

    const int b = blockIdx.y;
    const int pix = blockIdx.x * 128 + tid;

    float acc[32];
#pragma unroll
    for (int o = 0; o < 32; o++) acc[o] = by[o];

#pragma unroll 4
    for (int ic = 0; ic < 32; ++ic) {
        float v = hx2[(long)b * SB + ic * HW + pix];
#pragma unroll
        for (int o = 0; o < 32; o++) acc[o] = fmaf(v, wsm[o * 64 + ic], acc[o]);
    }
#pragma unroll 4
    for (int ic = 0; ic < 32; ++ic) {
        float v = hz2[(long)b * SB + ic * HW + pix];
#pragma unroll
        for (int o = 0; o < 32; o++) acc[o] = fmaf(v, wsm[o * 64 + 32 + ic], acc[o]);
    }
#pragma unroll
    for (int o = 0; o < 32; o++) y[(long)b * 32 * HW + o * HW + pix] = acc[o];
}

// ---------------- final 1x1 conv (32 -> 1) ----------------
__global__ void final_kernel(const float* __restrict__ y, const float* __restrict__ wl,
                             float* __restrict__ pred, float* __restrict__ outp)
{
    const int i = blockIdx.x * 256 + threadIdx.x;
    const int b = i >> 12, pix = i & 4095;
    float a = 0.f;
#pragma unroll
    for (int oc = 0; oc < 32; ++oc) a = fmaf(wl[oc], y[(long)b * 32 * HW + oc * HW + pix], a);
    pred[i] = a;
    if (outp) outp[(long)b * 10 * HW + pix] = a;
}

// ---------------- host orchestration ----------------
extern "C" void kernel_launch(void* const* d_in, const int* in_sizes, int n_in,
                              void* d_out, int out_size)
{
    const float* in     = (const float*)d_in[0];
    const float* w_x0   = (const float*)d_in[1];
    const float* b_x0   = (const float*)d_in[2];
    const float* w_z0   = (const float*)d_in[3];
    const float* b_z0   = (const float*)d_in[4];
    const float* w_y0   = (const float*)d_in[5];
    const float* b_y0   = (const float*)d_in[6];
    const float* w_x1   = (const float*)d_in[7];
    const float* b_x1   = (const float*)d_in[8];
    const float* w_z1   = (const float*)d_in[9];
    const float* b_z1   = (const float*)d_in[10];
    const float* w_y1   = (const float*)d_in[11];
    const float* b_y1   = (const float*)d_in[12];
    const float* w_last = (const float*)d_in[13];
    float* out = (float*)d_out;

    float *sx0, *szp, *sx1, *sx2, *yb, *pred, *wx0t, *wz0t, *wx1t, *wz1t;
    cudaGetSymbolAddress((void**)&sx0,  g_sx0);
    cudaGetSymbolAddress((void**)&szp,  g_sz);
    cudaGetSymbolAddress((void**)&sx1,  g_sx1);
    cudaGetSymbolAddress((void**)&sx2,  g_sx2);
    cudaGetSymbolAddress((void**)&yb,   g_y);
    cudaGetSymbolAddress((void**)&pred, g_pred);
    cudaGetSymbolAddress((void**)&wx0t, g_wx0t);
    cudaGetSymbolAddress((void**)&wz0t, g_wz0t);
    cudaGetSymbolAddress((void**)&wx1t, g_wx1t);
    cudaGetSymbolAddress((void**)&wz1t, g_wz1t);

    cudaMemsetAsync(sx0, 0, sizeof(float) * 3 * 2 * STATE_ELEMS, 0);
    cudaMemsetAsync(szp, 0, sizeof(float) * 3 * 2 * STATE_ELEMS, 0);

    {
        long total = NA + NBW + NC + ND;
        transpose_all<<<(int)((total + 255) / 256), 256>>>(w_x0, w_z0, w_x1, w_z1,
                                                           wx0t, wz0t, wx1t, wz1t);
    }

    for (int step = 0; step < STEPS; ++step) {
        const int idx = step + 2;
        for (int l = 0; l < 3; ++l) {
            for (int s = 0; s < 3; ++s) {
                const float* xptr; int xbs;
                if (l == 0) {
                    int t = idx - 2 + s;
                    if (t < T_IN) { xptr = in + (long)t * HW;              xbs = T_IN * HW; }
                    else          { xptr = pred + (long)(t - 3) * NB * HW; xbs = HW; }
                } else {
                    xptr = yb + (((l - 1) & 1) * 3 + s) * (long)YBUF_ELEMS;
                    xbs = 32 * HW;
                }
                float* srcx = (s == 0) ? sx0 + (l * 2 + (step & 1)) * (long)STATE_ELEMS
                            : (s == 1) ? sx0 + (l * 2 + ((step + 1) & 1)) * (long)STATE_ELEMS
                                       : sx1 + l * (long)STATE_ELEMS;
                float* dstx = (s == 0) ? sx0 + (l * 2 + ((step + 1) & 1)) * (long)STATE_ELEMS
                            : (s == 1) ? sx1 + l * (long)STATE_ELEMS
                                       : sx2 + l * (long)STATE_ELEMS;
                const int k = step * 3 + s;
                float* srcz = szp + (l * 2 + (k & 1)) * (long)STATE_ELEMS;
                float* dstz = szp + (l * 2 + ((k + 1) & 1)) * (long)STATE_ELEMS;

                const float *wxt, *bx, *wzt, *bz, *wy, *by;
                if (l == 0) {
                    wxt = wx0t + (long)s * 65 * 9 * 128;   bx = b_x0 + s * 128;
                    wzt = wz0t + (long)s * 65 * 25 * 128;  bz = b_z0 + s * 128;
                    wy  = w_y0 + (long)s * 32 * 64;        by = b_y0 + s * 32;
                } else {
                    int q = (l - 1) * 3 + s;
                    wxt = wx1t + (long)q * 96 * 9 * 128;   bx = b_x1 + q * 128;
                    wzt = wz1t + (long)q * 96 * 25 * 128;  bz = b_z1 + q * 128;
                    wy  = w_y1 + (long)q * 32 * 64;        by = b_y1 + q * 32;
                }

                if (l == 0)
                    cell_kernel<1><<<512, 256>>>(xptr, xbs, srcx, srcz, wxt, bx, wzt, bz, dstx, dstz);
                else
                    cell_kernel<32><<<512, 256>>>(xptr, xbs, srcx, srcz, wxt, bx, wzt, bz, dstx, dstz);

                float* ydst = yb + ((l & 1) * 3 + s) * (long)YBUF_ELEMS;
                conv_y_kernel<<<dim3(32, 4), 128>>>(dstx, dstz, wy, by, ydst);
            }
        }
        float* ylast = yb + (0 * 3 + 2) * (long)YBUF_ELEMS;
        float* predp = pred + (long)step * NB * HW;
        float* outp  = (step >= 8) ? out + (long)(step - 8) * HW : nullptr;
        final_kernel<<<64, 256>>>(ylast, w_last, predp, outp);
    }
}

// round 5
// speedup vs baseline: 1.1783x; 1.1783x over previous
#include <cuda_runtime.h>
#include <cmath>
#include <cstdint>

// ---------------- problem constants ----------------
#define HW   4096
#define SB   (64*HW)
#define NB   4
#define T_IN 10
#define STEPS 18
#define STATE_ELEMS (NB*64*HW)
#define YBUF_ELEMS  (NB*32*HW)

// ---------------- device scratch ----------------
__device__ float g_sx0[3*2*STATE_ELEMS];
__device__ float g_sz [3*2*STATE_ELEMS];
__device__ float g_sx1[3*STATE_ELEMS];
__device__ float g_sx2[3*STATE_ELEMS];
__device__ float g_y  [2*3*YBUF_ELEMS];
__device__ float g_pred[STEPS*NB*HW];

// transposed weights: [set][cin][tap][gate'] gate' = chunk*16 + j*4 + g  (8 chunks)
__device__ float g_wx0t[3*65*9*128];
__device__ float g_wz0t[3*65*25*128];
__device__ float g_wx1t[6*96*9*128];
__device__ float g_wz1t[6*96*25*128];

__device__ __forceinline__ float sigf(float x) { return 1.0f / (1.0f + expf(-x)); }

__device__ __forceinline__ unsigned sptr(const void* p) {
    return (unsigned)__cvta_generic_to_shared(p);
}
__device__ __forceinline__ void cpa16p(unsigned d, const void* s, bool ok) {
    asm volatile("cp.async.cg.shared.global [%0], [%1], 16, %2;"
                 :: "r"(d), "l"(s), "r"(ok ? 16 : 0));
}
__device__ __forceinline__ void cpa16(unsigned d, const void* s) {
    asm volatile("cp.async.cg.shared.global [%0], [%1], 16;" :: "r"(d), "l"(s));
}
#define CP_COMMIT() asm volatile("cp.async.commit_group;")
template<int N> __device__ __forceinline__ void cp_wait() {
    asm volatile("cp.async.wait_group %0;" :: "n"(N));
}
#define FFMA2(acc, a, b) asm("fma.rn.f32x2 %0, %1, %2, %0;" : "+l"(acc) : "l"(a), "l"(b))

// ---------------- fused weight pre-transpose ----------------
// gp = chunk*16 + j*4 + g; hid = chunk*4+j; gc = g*32 + hid
__device__ __forceinline__ void transpose_one(const float* __restrict__ src,
                                              float* __restrict__ dst,
                                              int cin, int kk, long i)
{
    int gp = (int)(i & 127);
    long r = i >> 7;
    int tap = (int)(r % kk); r /= kk;
    int ci  = (int)(r % cin);
    int set = (int)(r / cin);
    int chunk = gp >> 4, rem = gp & 15, j = rem >> 2, g = rem & 3;
    int gc = g * 32 + chunk * 4 + j;
    dst[i] = src[(((long)set * 128 + gc) * cin + ci) * kk + tap];
}

#define NA  ((long)3*65*9*128)
#define NBW ((long)3*65*25*128)
#define NC  ((long)6*96*9*128)
#define ND  ((long)6*96*25*128)

__global__ void transpose_all(const float* __restrict__ wx0, const float* __restrict__ wz0,
                              const float* __restrict__ wx1, const float* __restrict__ wz1,
                              float* __restrict__ dx0, float* __restrict__ dz0,
                              float* __restrict__ dx1, float* __restrict__ dz1)
{
    long i = (long)blockIdx.x * 256 + threadIdx.x;
    if (i < NA)  { transpose_one(wx0, dx0, 65, 9,  i); return; }
    i -= NA;
    if (i < NBW) { transpose_one(wz0, dz0, 65, 25, i); return; }
    i -= NBW;
    if (i < NC)  { transpose_one(wx1, dx1, 96, 9,  i); return; }
    i -= NC;
    if (i < ND)  { transpose_one(wz1, dz1, 96, 25, i); }
}

// ---------------- fused conv + LSTM gating ----------------
// Block covers full 64-px width x 16 rows; thread owns 4 px (tx, +16, +32, +48)
// and 4 hidden channels (16 gates). Tile rows stored at col offset 4 (halo zeros
// live in cols [0,4) and [68,72); stride 80 -> warp's two rows use disjoint banks).
#define TSTRIDE 80
#define TROWS   20
template<int K, int CINX>
__device__ __forceinline__ void conv_branch(
    const float* __restrict__ x, int xbs,
    const float* __restrict__ hx, const float* __restrict__ hz,
    const float* __restrict__ cstate,
    const float* __restrict__ wt, const float* __restrict__ bias,
    float* __restrict__ dst,
    float* tileb, float* wb, int b, int chunk, int yt)
{
    constexpr int KK = K * K, PAD = K / 2;
    constexpr int TSY = 16 + K - 1;
    constexpr int CIN = CINX + 64;
    constexpr int WSZ = KK * 16;
    const int tx = threadIdx.x & 15, ty = threadIdx.x >> 4, tid = threadIdx.x;
    const int gy0 = yt * 16 - PAD;

    // zero the x-halo columns of all 3 buffers (never written by prefetch)
    for (int i = tid; i < 3 * TROWS * 8; i += 256) {
        int buf = i / (TROWS * 8), rr = (i / 8) % TROWS, c = i & 7;
        tileb[buf * (TROWS * TSTRIDE) + rr * TSTRIDE + (c < 4 ? c : 64 + c)] = 0.f;
    }

    auto chanptr = [&](int c) -> const float* {
        if (c < CINX)            return x  + (long)b * xbs + c * HW;
        else if (c < CINX + 32)  return hx + (long)b * SB + (c - CINX) * HW;
        else                     return hz + (long)b * SB + (c - CINX - 32) * HW;
    };
    auto prefetch = [&](int c, int buf) {
        const float* p = chanptr(c);
        float* tb = tileb + buf * (TROWS * TSTRIDE);
#pragma unroll
        for (int i = tid; i < TSY * 16; i += 256) {
            int row = i >> 4, q = i & 15;
            int yy = gy0 + row;
            bool ok = (yy >= 0 && yy < 64);
            cpa16p(sptr(tb + row * TSTRIDE + 4 + q * 4), ok ? p + yy * 64 + q * 4 : p, ok);
        }
        if (tid < KK * 4) {
            int tap = tid >> 2, off = tid & 3;
            const float* src = wt + (((long)c * KK + tap) << 7) + chunk * 16 + off * 4;
            cpa16(sptr(wb + buf * WSZ + tap * 16 + off * 4), src);
        }
        CP_COMMIT();
    };

    unsigned long long acc[4][8];
#pragma unroll
    for (int i = 0; i < 4; i++)
#pragma unroll
        for (int j = 0; j < 8; j++) acc[i][j] = 0ull;

    prefetch(0, 0);
    for (int c = 0; c < CIN; ++c) {
        if (c + 1 < CIN) { prefetch(c + 1, (c + 1) % 3); cp_wait<1>(); }
        else             { cp_wait<0>(); }
        __syncthreads();
        const float* tb = tileb + (c % 3) * (TROWS * TSTRIDE);
        const float* wp = wb + (c % 3) * WSZ;
#pragma unroll
        for (int ky = 0; ky < K; ++ky)
#pragma unroll
        for (int kx = 0; kx < K; ++kx) {
            const float* rowp = tb + (ty + ky) * TSTRIDE + 4 + tx + kx - PAD;
            unsigned long long vv[4];
#pragma unroll
            for (int i = 0; i < 4; i++) {
                float v = rowp[i * 16];
                asm("mov.b64 %0, {%1, %1};" : "=l"(vv[i]) : "f"(v));
            }
            const ulonglong2* wq = (const ulonglong2*)(wp + (ky * K + kx) * 16);
#pragma unroll
            for (int p = 0; p < 4; p++) {
                ulonglong2 w2 = wq[p];
#pragma unroll
                for (int i = 0; i < 4; i++) {
                    FFMA2(acc[i][2 * p],     vv[i], w2.x);
                    FFMA2(acc[i][2 * p + 1], vv[i], w2.y);
                }
            }
        }
    }

    const int pixb = (yt * 16 + ty) * 64 + tx;
#pragma unroll
    for (int j = 0; j < 4; j++) {
        int hid = chunk * 4 + j;
        float bi = bias[hid], bf = bias[32 + hid] + 0.01f, bg = bias[64 + hid], bo = bias[96 + hid];
#pragma unroll
        for (int i = 0; i < 4; i++) {
            float ai, af, ag, ao;
            asm("mov.b64 {%0, %1}, %2;" : "=f"(ai), "=f"(af) : "l"(acc[i][2 * j]));
            asm("mov.b64 {%0, %1}, %2;" : "=f"(ag), "=f"(ao) : "l"(acc[i][2 * j + 1]));
            int pix = pixb + i * 16;
            float gi = sigf(ai + bi);
            float gf = sigf(af + bf);
            float gg = tanhf(ag + bg);
            float go = sigf(ao + bo);
            float cold = cstate[(long)b * SB + (32 + hid) * HW + pix];
            float cnew = gf * cold + gi * gg;
            dst[(long)b * SB + hid * HW + pix]        = go * tanhf(cnew);
            dst[(long)b * SB + (32 + hid) * HW + pix] = cnew;
        }
    }
}

// ---------------- fused cell kernel ----------------
// 256 blocks, 2/SM. branch = bit2 of bid so the two same-SM blocks (bid, bid+148)
// get opposite branches -> balanced K3/K5 warp mix per SM.
template<int CINX>
__global__ __launch_bounds__(256, 2) void cell_kernel(
    const float* __restrict__ x, int xbs,
    const float* __restrict__ srcx, const float* __restrict__ srcz,
    const float* __restrict__ wxt, const float* __restrict__ bx,
    const float* __restrict__ wzt, const float* __restrict__ bz,
    float* __restrict__ dstx, float* __restrict__ dstz)
{
    __shared__ float tileb[3 * TROWS * TSTRIDE];
    __shared__ __align__(16) float wb[3 * 400];
    const int bid = blockIdx.x;
    const int branch = (bid >> 2) & 1;
    const int r = (bid & 3) | ((bid >> 3) << 2);   // 7 bits -> 0..127
    const int yt = r & 3, b = (r >> 2) & 3, chunk = (r >> 4) & 7;
    if (branch == 0)
        conv_branch<3, CINX>(x, xbs, srcx, srcz, srcx, wxt, bx, dstx, tileb, wb, b, chunk, yt);
    else
        conv_branch<5, CINX>(x, xbs, srcx, srcz, srcz, wzt, bz, dstz, tileb, wb, b, chunk, yt);
}

// ---------------- 1x1 output conv ----------------
__global__ __launch_bounds__(128) void conv_y_kernel(
    const float* __restrict__ hx2, const float* __restrict__ hz2,
    const float* __restrict__ wy, const float* __restrict__ by,
    float* __restrict__ y)
{
    __shared__ float wsm[32 * 64];
    const int tid = threadIdx.x;
    for (int i = tid; i < 2048; i += 128) wsm[i] = wy[i];
    __syncthreads();

    const int b = blockIdx.y;
    const int pix = blockIdx.x * 128 + tid;

    float acc[32];
#pragma unroll
    for (int o = 0; o < 32; o++) acc[o] = by[o];

#pragma unroll 4
    for (int ic = 0; ic < 32; ++ic) {
        float v = hx2[(long)b * SB + ic * HW + pix];
#pragma unroll
        for (int o = 0; o < 32; o++) acc[o] = fmaf(v, wsm[o * 64 + ic], acc[o]);
    }
#pragma unroll 4
    for (int ic = 0; ic < 32; ++ic) {
        float v = hz2[(long)b * SB + ic * HW + pix];
#pragma unroll
        for (int o = 0; o < 32; o++) acc[o] = fmaf(v, wsm[o * 64 + 32 + ic], acc[o]);
    }
#pragma unroll
    for (int o = 0; o < 32; o++) y[(long)b * 32 * HW + o * HW + pix] = acc[o];
}

// ---------------- final 1x1 conv (32 -> 1) ----------------
__global__ void final_kernel(const float* __restrict__ y, const float* __restrict__ wl,
                             float* __restrict__ pred, float* __restrict__ outp)
{
    const int i = blockIdx.x * 256 + threadIdx.x;
    const int b = i >> 12, pix = i & 4095;
    float a = 0.f;
#pragma unroll
    for (int oc = 0; oc < 32; ++oc) a = fmaf(wl[oc], y[(long)b * 32 * HW + oc * HW + pix], a);
    pred[i] = a;
    if (outp) outp[(long)b * 10 * HW + pix] = a;
}

// ---------------- host orchestration ----------------
extern "C" void kernel_launch(void* const* d_in, const int* in_sizes, int n_in,
                              void* d_out, int out_size)
{
    const float* in     = (const float*)d_in[0];
    const float* w_x0   = (const float*)d_in[1];
    const float* b_x0   = (const float*)d_in[2];
    const float* w_z0   = (const float*)d_in[3];
    const float* b_z0   = (const float*)d_in[4];
    const float* w_y0   = (const float*)d_in[5];
    const float* b_y0   = (const float*)d_in[6];
    const float* w_x1   = (const float*)d_in[7];
    const float* b_x1   = (const float*)d_in[8];
    const float* w_z1   = (const float*)d_in[9];
    const float* b_z1   = (const float*)d_in[10];
    const float* w_y1   = (const float*)d_in[11];
    const float* b_y1   = (const float*)d_in[12];
    const float* w_last = (const float*)d_in[13];
    float* out = (float*)d_out;

    float *sx0, *szp, *sx1, *sx2, *yb, *pred, *wx0t, *wz0t, *wx1t, *wz1t;
    cudaGetSymbolAddress((void**)&sx0,  g_sx0);
    cudaGetSymbolAddress((void**)&szp,  g_sz);
    cudaGetSymbolAddress((void**)&sx1,  g_sx1);
    cudaGetSymbolAddress((void**)&sx2,  g_sx2);
    cudaGetSymbolAddress((void**)&yb,   g_y);
    cudaGetSymbolAddress((void**)&pred, g_pred);
    cudaGetSymbolAddress((void**)&wx0t, g_wx0t);
    cudaGetSymbolAddress((void**)&wz0t, g_wz0t);
    cudaGetSymbolAddress((void**)&wx1t, g_wx1t);
    cudaGetSymbolAddress((void**)&wz1t, g_wz1t);

    cudaMemsetAsync(sx0, 0, sizeof(float) * 3 * 2 * STATE_ELEMS, 0);
    cudaMemsetAsync(szp, 0, sizeof(float) * 3 * 2 * STATE_ELEMS, 0);

    {
        long total = NA + NBW + NC + ND;
        transpose_all<<<(int)((total + 255) / 256), 256>>>(w_x0, w_z0, w_x1, w_z1,
                                                           wx0t, wz0t, wx1t, wz1t);
    }

    for (int step = 0; step < STEPS; ++step) {
        const int idx = step + 2;
        for (int l = 0; l < 3; ++l) {
            for (int s = 0; s < 3; ++s) {
                const float* xptr; int xbs;
                if (l == 0) {
                    int t = idx - 2 + s;
                    if (t < T_IN) { xptr = in + (long)t * HW;              xbs = T_IN * HW; }
                    else          { xptr = pred + (long)(t - 3) * NB * HW; xbs = HW; }
                } else {
                    xptr = yb + (((l - 1) & 1) * 3 + s) * (long)YBUF_ELEMS;
                    xbs = 32 * HW;
                }
                float* srcx = (s == 0) ? sx0 + (l * 2 + (step & 1)) * (long)STATE_ELEMS
                            : (s == 1) ? sx0 + (l * 2 + ((step + 1) & 1)) * (long)STATE_ELEMS
                                       : sx1 + l * (long)STATE_ELEMS;
                float* dstx = (s == 0) ? sx0 + (l * 2 + ((step + 1) & 1)) * (long)STATE_ELEMS
                            : (s == 1) ? sx1 + l * (long)STATE_ELEMS
                                       : sx2 + l * (long)STATE_ELEMS;
                const int k = step * 3 + s;
                float* srcz = szp + (l * 2 + (k & 1)) * (long)STATE_ELEMS;
                float* dstz = szp + (l * 2 + ((k + 1) & 1)) * (long)STATE_ELEMS;

                const float *wxt, *bx, *wzt, *bz, *wy, *by;
                if (l == 0) {
                    wxt = wx0t + (long)s * 65 * 9 * 128;   bx = b_x0 + s * 128;
                    wzt = wz0t + (long)s * 65 * 25 * 128;  bz = b_z0 + s * 128;
                    wy  = w_y0 + (long)s * 32 * 64;        by = b_y0 + s * 32;
                } else {
                    int q = (l - 1) * 3 + s;
                    wxt = wx1t + (long)q * 96 * 9 * 128;   bx = b_x1 + q * 128;
                    wzt = wz1t + (long)q * 96 * 25 * 128;  bz = b_z1 + q * 128;
                    wy  = w_y1 + (long)q * 32 * 64;        by = b_y1 + q * 32;
                }

                if (l == 0)
                    cell_kernel<1><<<256, 256>>>(xptr, xbs, srcx, srcz, wxt, bx, wzt, bz, dstx, dstz);
                else
                    cell_kernel<32><<<256, 256>>>(xptr, xbs, srcx, srcz, wxt, bx, wzt, bz, dstx, dstz);

                float* ydst = yb + ((l & 1) * 3 + s) * (long)YBUF_ELEMS;
                conv_y_kernel<<<dim3(32, 4), 128>>>(dstx, dstz, wy, by, ydst);
            }
        }
        float* ylast = yb + (0 * 3 + 2) * (long)YBUF_ELEMS;
        float* predp = pred + (long)step * NB * HW;
        float* outp  = (step >= 8) ? out + (long)(step - 8) * HW : nullptr;
        final_kernel<<<64, 256>>>(ylast, w_last, predp, outp);
    }
}

// round 6
// speedup vs baseline: 1.6788x; 1.4247x over previous
#include <cuda_runtime.h>
#include <cmath>
#include <cstdint>

// ---------------- problem constants ----------------
#define HW   4096
#define SB   (64*HW)
#define NB   4
#define T_IN 10
#define STEPS 18
#define STATE_ELEMS (NB*64*HW)
#define YBUF_ELEMS  (NB*32*HW)

// ---------------- device scratch ----------------
__device__ float g_sx0[3*2*STATE_ELEMS];
__device__ float g_sz [3*2*STATE_ELEMS];
__device__ float g_sx1[3*STATE_ELEMS];
__device__ float g_sx2[3*STATE_ELEMS];
__device__ float g_y  [2*3*YBUF_ELEMS];
__device__ float g_pred[STEPS*NB*HW];

// transposed weights: [set][cin][tap][gate'] gate' = chunk*8 + j*4 + g (16 chunks of 2 hid)
__device__ float g_wx0t[3*65*9*128];
__device__ float g_wz0t[3*65*25*128];
__device__ float g_wx1t[6*96*9*128];
__device__ float g_wz1t[6*96*25*128];

__device__ __forceinline__ float sigf(float x) { return 1.0f / (1.0f + expf(-x)); }

__device__ __forceinline__ unsigned sptr(const void* p) {
    return (unsigned)__cvta_generic_to_shared(p);
}
__device__ __forceinline__ void cpa16p(unsigned d, const void* s, bool ok) {
    asm volatile("cp.async.cg.shared.global [%0], [%1], 16, %2;"
                 :: "r"(d), "l"(s), "r"(ok ? 16 : 0));
}
__device__ __forceinline__ void cpa16(unsigned d, const void* s) {
    asm volatile("cp.async.cg.shared.global [%0], [%1], 16;" :: "r"(d), "l"(s));
}
#define CP_COMMIT() asm volatile("cp.async.commit_group;")
template<int N> __device__ __forceinline__ void cp_wait() {
    asm volatile("cp.async.wait_group %0;" :: "n"(N));
}
#define FFMA2(acc, a, b) asm("fma.rn.f32x2 %0, %1, %2, %0;" : "+l"(acc) : "l"(a), "l"(b))

// ---------------- fused weight pre-transpose ----------------
// gp = chunk*8 + j*4 + g  (chunk 0..15, j 0..1, g 0..3); hid = chunk*2+j; gc = g*32 + hid
__device__ __forceinline__ void transpose_one(const float* __restrict__ src,
                                              float* __restrict__ dst,
                                              int cin, int kk, long i)
{
    int gp = (int)(i & 127);
    long r = i >> 7;
    int tap = (int)(r % kk); r /= kk;
    int ci  = (int)(r % cin);
    int set = (int)(r / cin);
    int chunk = gp >> 3, rem = gp & 7, j = rem >> 2, g = rem & 3;
    int gc = g * 32 + chunk * 2 + j;
    dst[i] = src[(((long)set * 128 + gc) * cin + ci) * kk + tap];
}

#define NA  ((long)3*65*9*128)
#define NBW ((long)3*65*25*128)
#define NC  ((long)6*96*9*128)
#define ND  ((long)6*96*25*128)

__global__ void transpose_all(const float* __restrict__ wx0, const float* __restrict__ wz0,
                              const float* __restrict__ wx1, const float* __restrict__ wz1,
                              float* __restrict__ dx0, float* __restrict__ dz0,
                              float* __restrict__ dx1, float* __restrict__ dz1)
{
    long i = (long)blockIdx.x * 256 + threadIdx.x;
    if (i < NA)  { transpose_one(wx0, dx0, 65, 9,  i); return; }
    i -= NA;
    if (i < NBW) { transpose_one(wz0, dz0, 65, 25, i); return; }
    i -= NBW;
    if (i < NC)  { transpose_one(wx1, dx1, 96, 9,  i); return; }
    i -= NC;
    if (i < ND)  { transpose_one(wz1, dz1, 96, 25, i); }
}

// ---------------- fused dual-branch conv + LSTM gating ----------------
// Block: 256 threads (16x16), covers 16 rows x 64 cols; thread owns 4 ADJACENT px
// (cols tx*4..tx*4+3) and 2 hidden channels of BOTH branches (8 gates each).
// K3 taps share the K5 row-cache and duplicated vv operands.
#define TSTRIDE 80
#define TROWS   20
#define WCH     272   // per-buffer weight floats: 25*8 (K5) + 9*8 (K3)
template<int CINX>
__global__ __launch_bounds__(256, 2) void cell_kernel(
    const float* __restrict__ x, int xbs,
    const float* __restrict__ srcx, const float* __restrict__ srcz,
    const float* __restrict__ wxt, const float* __restrict__ bx,
    const float* __restrict__ wzt, const float* __restrict__ bz,
    float* __restrict__ dstx, float* __restrict__ dstz)
{
    constexpr int CIN = CINX + 64;
    __shared__ float tileb[3 * TROWS * TSTRIDE];
    __shared__ __align__(16) float wb[3 * WCH];

    const int tx = threadIdx.x & 15, ty = threadIdx.x >> 4, tid = threadIdx.x;
    const int bid = blockIdx.x;
    const int chunk = bid >> 4;           // 0..15 (2 hidden ch)
    const int b  = (bid >> 2) & 3;
    const int yt = bid & 3;
    const int gy0 = yt * 16 - 2;          // K5 pad

    // zero x-halo cols 0..3 and 68..71 of all 3 tile buffers
    for (int i = tid; i < 3 * TROWS * 8; i += 256) {
        int buf = i / (TROWS * 8), rr = (i / 8) % TROWS, c = i & 7;
        tileb[buf * (TROWS * TSTRIDE) + rr * TSTRIDE + (c < 4 ? c : 64 + c)] = 0.f;
    }

    auto chanptr = [&](int c) -> const float* {
        if (c < CINX)            return x  + (long)b * xbs + c * HW;
        else if (c < CINX + 32)  return srcx + (long)b * SB + (c - CINX) * HW;
        else                     return srcz + (long)b * SB + (c - CINX - 32) * HW;
    };
    auto prefetch = [&](int c, int buf) {
        const float* p = chanptr(c);
        float* tb = tileb + buf * (TROWS * TSTRIDE);
#pragma unroll
        for (int i = tid; i < TROWS * 16; i += 256) {
            int row = i >> 4, q = i & 15;
            int yy = gy0 + row;
            bool ok = (yy >= 0 && yy < 64);
            cpa16p(sptr(tb + row * TSTRIDE + 4 + q * 4), ok ? p + yy * 64 + q * 4 : p, ok);
        }
        // weights: K5 -> wb[0..199], K3 -> wb[200..271]
        if (tid < 68) {
            if (tid < 50) {
                int tap = tid >> 1, half = tid & 1;
                cpa16(sptr(wb + buf * WCH + tap * 8 + half * 4),
                      wzt + (((long)c * 25 + tap) << 7) + chunk * 8 + half * 4);
            } else {
                int t = tid - 50, tap = t >> 1, half = t & 1;
                cpa16(sptr(wb + buf * WCH + 200 + tap * 8 + half * 4),
                      wxt + (((long)c * 9 + tap) << 7) + chunk * 8 + half * 4);
            }
        }
        CP_COMMIT();
    };

    unsigned long long a5[4][4], a3[4][4];   // [px][hid0(i,f),hid0(g,o),hid1(i,f),hid1(g,o)]
#pragma unroll
    for (int i = 0; i < 4; i++)
#pragma unroll
        for (int j = 0; j < 4; j++) { a5[i][j] = 0ull; a3[i][j] = 0ull; }

    prefetch(0, 0);
    for (int c = 0; c < CIN; ++c) {
        if (c + 1 < CIN) { prefetch(c + 1, (c + 1) % 3); cp_wait<1>(); }
        else             { cp_wait<0>(); }
        __syncthreads();
        const float* tb = tileb + (c % 3) * (TROWS * TSTRIDE);
        const float* w5 = wb + (c % 3) * WCH;
        const float* w3 = w5 + 200;
#pragma unroll
        for (int ky = 0; ky < 5; ++ky) {
            // row cache: 12 floats covering cols tx*4-4 .. tx*4+7 (tile coords)
            const float* rowp = tb + (ty + ky) * TSTRIDE + tx * 4;
            float4 r0 = *(const float4*)(rowp);
            float4 r1 = *(const float4*)(rowp + 4);
            float4 r2 = *(const float4*)(rowp + 8);
            float cache[12] = {r0.x, r0.y, r0.z, r0.w, r1.x, r1.y, r1.z, r1.w,
                               r2.x, r2.y, r2.z, r2.w};
#pragma unroll
            for (int kx = 0; kx < 5; ++kx) {
                unsigned long long vv[4];
#pragma unroll
                for (int p = 0; p < 4; p++) {
                    float v = cache[p + kx + 2];
                    asm("mov.b64 %0, {%1, %1};" : "=l"(vv[p]) : "f"(v));
                }
                {   // K5 tap
                    const ulonglong2* wq = (const ulonglong2*)(w5 + (ky * 5 + kx) * 8);
                    ulonglong2 wA = wq[0];   // hid0: (i,f),(g,o)
                    ulonglong2 wB = wq[1];   // hid1
#pragma unroll
                    for (int p = 0; p < 4; p++) {
                        FFMA2(a5[p][0], vv[p], wA.x);
                        FFMA2(a5[p][1], vv[p], wA.y);
                        FFMA2(a5[p][2], vv[p], wB.x);
                        FFMA2(a5[p][3], vv[p], wB.y);
                    }
                }
                if (ky >= 1 && ky <= 3 && kx >= 1 && kx <= 3) {   // K3 tap (same vv)
                    const ulonglong2* wq = (const ulonglong2*)(w3 + ((ky - 1) * 3 + (kx - 1)) * 8);
                    ulonglong2 wA = wq[0];
                    ulonglong2 wB = wq[1];
#pragma unroll
                    for (int p = 0; p < 4; p++) {
                        FFMA2(a3[p][0], vv[p], wA.x);
                        FFMA2(a3[p][1], vv[p], wA.y);
                        FFMA2(a3[p][2], vv[p], wB.x);
                        FFMA2(a3[p][3], vv[p], wB.y);
                    }
                }
            }
        }
    }

    const int pixb = (yt * 16 + ty) * 64 + tx * 4;
#pragma unroll
    for (int j = 0; j < 2; j++) {
        const int hid = chunk * 2 + j;
        // K3 (x-branch): c-state from srcx, write dstx
        float bi = bx[hid], bf = bx[32 + hid] + 0.01f, bg = bx[64 + hid], bo = bx[96 + hid];
#pragma unroll
        for (int p = 0; p < 4; p++) {
            float ai, af, ag, ao;
            asm("mov.b64 {%0, %1}, %2;" : "=f"(ai), "=f"(af) : "l"(a3[p][j * 2]));
            asm("mov.b64 {%0, %1}, %2;" : "=f"(ag), "=f"(ao) : "l"(a3[p][j * 2 + 1]));
            int pix = pixb + p;
            float gi = sigf(ai + bi), gf = sigf(af + bf);
            float gg = tanhf(ag + bg), go = sigf(ao + bo);
            float cold = srcx[(long)b * SB + (32 + hid) * HW + pix];
            float cnew = gf * cold + gi * gg;
            dstx[(long)b * SB + hid * HW + pix]        = go * tanhf(cnew);
            dstx[(long)b * SB + (32 + hid) * HW + pix] = cnew;
        }
        // K5 (z-branch): c-state from srcz, write dstz
        bi = bz[hid]; bf = bz[32 + hid] + 0.01f; bg = bz[64 + hid]; bo = bz[96 + hid];
#pragma unroll
        for (int p = 0; p < 4; p++) {
            float ai, af, ag, ao;
            asm("mov.b64 {%0, %1}, %2;" : "=f"(ai), "=f"(af) : "l"(a5[p][j * 2]));
            asm("mov.b64 {%0, %1}, %2;" : "=f"(ag), "=f"(ao) : "l"(a5[p][j * 2 + 1]));
            int pix = pixb + p;
            float gi = sigf(ai + bi), gf = sigf(af + bf);
            float gg = tanhf(ag + bg), go = sigf(ao + bo);
            float cold = srcz[(long)b * SB + (32 + hid) * HW + pix];
            float cnew = gf * cold + gi * gg;
            dstz[(long)b * SB + hid * HW + pix]        = go * tanhf(cnew);
            dstz[(long)b * SB + (32 + hid) * HW + pix] = cnew;
        }
    }
}

// ---------------- 1x1 output conv ----------------
__global__ __launch_bounds__(128) void conv_y_kernel(
    const float* __restrict__ hx2, const float* __restrict__ hz2,
    const float* __restrict__ wy, const float* __restrict__ by,
    float* __restrict__ y)
{
    __shared__ float wsm[32 * 64];
    const int tid = threadIdx.x;
    for (int i = tid; i < 2048; i += 128) wsm[i] = wy[i];
    __syncthreads();

    const int b = blockIdx.y;
    const int pix = blockIdx.x * 128 + tid;

    float acc[32];
#pragma unroll
    for (int o = 0; o < 32; o++) acc[o] = by[o];

#pragma unroll 4
    for (int ic = 0; ic < 32; ++ic) {
        float v = hx2[(long)b * SB + ic * HW + pix];
#pragma unroll
        for (int o = 0; o < 32; o++) acc[o] = fmaf(v, wsm[o * 64 + ic], acc[o]);
    }
#pragma unroll 4
    for (int ic = 0; ic < 32; ++ic) {
        float v = hz2[(long)b * SB + ic * HW + pix];
#pragma unroll
        for (int o = 0; o < 32; o++) acc[o] = fmaf(v, wsm[o * 64 + 32 + ic], acc[o]);
    }
#pragma unroll
    for (int o = 0; o < 32; o++) y[(long)b * 32 * HW + o * HW + pix] = acc[o];
}

// ---------------- final 1x1 conv (32 -> 1) ----------------
__global__ void final_kernel(const float* __restrict__ y, const float* __restrict__ wl,
                             float* __restrict__ pred, float* __restrict__ outp)
{
    const int i = blockIdx.x * 256 + threadIdx.x;
    const int b = i >> 12, pix = i & 4095;
    float a = 0.f;
#pragma unroll
    for (int oc = 0; oc < 32; ++oc) a = fmaf(wl[oc], y[(long)b * 32 * HW + oc * HW + pix], a);
    pred[i] = a;
    if (outp) outp[(long)b * 10 * HW + pix] = a;
}

// ---------------- host orchestration ----------------
extern "C" void kernel_launch(void* const* d_in, const int* in_sizes, int n_in,
                              void* d_out, int out_size)
{
    const float* in     = (const float*)d_in[0];
    const float* w_x0   = (const float*)d_in[1];
    const float* b_x0   = (const float*)d_in[2];
    const float* w_z0   = (const float*)d_in[3];
    const float* b_z0   = (const float*)d_in[4];
    const float* w_y0   = (const float*)d_in[5];
    const float* b_y0   = (const float*)d_in[6];
    const float* w_x1   = (const float*)d_in[7];
    const float* b_x1   = (const float*)d_in[8];
    const float* w_z1   = (const float*)d_in[9];
    const float* b_z1   = (const float*)d_in[10];
    const float* w_y1   = (const float*)d_in[11];
    const float* b_y1   = (const float*)d_in[12];
    const float* w_last = (const float*)d_in[13];
    float* out = (float*)d_out;

    float *sx0, *szp, *sx1, *sx2, *yb, *pred, *wx0t, *wz0t, *wx1t, *wz1t;
    cudaGetSymbolAddress((void**)&sx0,  g_sx0);
    cudaGetSymbolAddress((void**)&szp,  g_sz);
    cudaGetSymbolAddress((void**)&sx1,  g_sx1);
    cudaGetSymbolAddress((void**)&sx2,  g_sx2);
    cudaGetSymbolAddress((void**)&yb,   g_y);
    cudaGetSymbolAddress((void**)&pred, g_pred);
    cudaGetSymbolAddress((void**)&wx0t, g_wx0t);
    cudaGetSymbolAddress((void**)&wz0t, g_wz0t);
    cudaGetSymbolAddress((void**)&wx1t, g_wx1t);
    cudaGetSymbolAddress((void**)&wz1t, g_wz1t);

    cudaMemsetAsync(sx0, 0, sizeof(float) * 3 * 2 * STATE_ELEMS, 0);
    cudaMemsetAsync(szp, 0, sizeof(float) * 3 * 2 * STATE_ELEMS, 0);

    {
        long total = NA + NBW + NC + ND;
        transpose_all<<<(int)((total + 255) / 256), 256>>>(w_x0, w_z0, w_x1, w_z1,
                                                           wx0t, wz0t, wx1t, wz1t);
    }

    for (int step = 0; step < STEPS; ++step) {
        const int idx = step + 2;
        for (int l = 0; l < 3; ++l) {
            for (int s = 0; s < 3; ++s) {
                const float* xptr; int xbs;
                if (l == 0) {
                    int t = idx - 2 + s;
                    if (t < T_IN) { xptr = in + (long)t * HW;              xbs = T_IN * HW; }
                    else          { xptr = pred + (long)(t - 3) * NB * HW; xbs = HW; }
                } else {
                    xptr = yb + (((l - 1) & 1) * 3 + s) * (long)YBUF_ELEMS;
                    xbs = 32 * HW;
                }
                float* srcx = (s == 0) ? sx0 + (l * 2 + (step & 1)) * (long)STATE_ELEMS
                            : (s == 1) ? sx0 + (l * 2 + ((step + 1) & 1)) * (long)STATE_ELEMS
                                       : sx1 + l * (long)STATE_ELEMS;
                float* dstx = (s == 0) ? sx0 + (l * 2 + ((step + 1) & 1)) * (long)STATE_ELEMS
                            : (s == 1) ? sx1 + l * (long)STATE_ELEMS
                                       : sx2 + l * (long)STATE_ELEMS;
                const int k = step * 3 + s;
                float* srcz = szp + (l * 2 + (k & 1)) * (long)STATE_ELEMS;
                float* dstz = szp + (l * 2 + ((k + 1) & 1)) * (long)STATE_ELEMS;

                const float *wxt, *bx, *wzt, *bz, *wy, *by;
                if (l == 0) {
                    wxt = wx0t + (long)s * 65 * 9 * 128;   bx = b_x0 + s * 128;
                    wzt = wz0t + (long)s * 65 * 25 * 128;  bz = b_z0 + s * 128;
                    wy  = w_y0 + (long)s * 32 * 64;        by = b_y0 + s * 32;
                } else {
                    int q = (l - 1) * 3 + s;
                    wxt = wx1t + (long)q * 96 * 9 * 128;   bx = b_x1 + q * 128;
                    wzt = wz1t + (long)q * 96 * 25 * 128;  bz = b_z1 + q * 128;
                    wy  = w_y1 + (long)q * 32 * 64;        by = b_y1 + q * 32;
                }

                if (l == 0)
                    cell_kernel<1><<<256, 256>>>(xptr, xbs, srcx, srcz, wxt, bx, wzt, bz, dstx, dstz);
                else
                    cell_kernel<32><<<256, 256>>>(xptr, xbs, srcx, srcz, wxt, bx, wzt, bz, dstx, dstz);

                float* ydst = yb + ((l & 1) * 3 + s) * (long)YBUF_ELEMS;
                conv_y_kernel<<<dim3(32, 4), 128>>>(dstx, dstz, wy, by, ydst);
            }
        }
        float* ylast = yb + (0 * 3 + 2) * (long)YBUF_ELEMS;
        float* predp = pred + (long)step * NB * HW;
        float* outp  = (step >= 8) ? out + (long)(step - 8) * HW : nullptr;
        final_kernel<<<64, 256>>>(ylast, w_last, predp, outp);
    }
}